// round 17
// baseline (speedup 1.0000x reference)
#include <cuda_runtime.h>

// Closed-form normalization constants.
#define Y00f  0.28209479177387814f    // 1/(2*sqrt(pi))
#define N10f  0.48860251190291992f    // sqrt(3/(4pi))
#define N20f  0.63078313050504001f    // sqrt(5/(4pi))
#define C21f  (-1.09254843059207907f) // -(1/2)*sqrt(15/pi)
#define C22f  0.54627421529603953f    // (1/4)*sqrt(15/pi)
#define K20f  0.35355339059327379f    // 1/(2*sqrt(2))
#define K21f  0.20412414523193152f    // 1/(2*sqrt(6))
#define K30f  0.06415002990995843f    // 1/(9*sqrt(3))
#define K31f  0.04536092116208279f    // sqrt(1/486)
#define K32f  0.02028602047074832f    // sqrt(8/19440)

typedef unsigned long long u64;

__device__ u64 g_A[14];   // pre-packed combined coefficients (lo==hi)

__device__ __forceinline__ u64 pk(float lo, float hi) {
    u64 r; asm("mov.b64 %0,{%1,%2};" : "=l"(r) : "f"(lo), "f"(hi)); return r;
}
__device__ __forceinline__ void upk(u64 v, float& lo, float& hi) {
    asm("mov.b64 {%0,%1},%2;" : "=f"(lo), "=f"(hi) : "l"(v));
}
__device__ __forceinline__ u64 f2mul(u64 a, u64 b) {
    u64 d; asm("mul.rn.f32x2 %0,%1,%2;" : "=l"(d) : "l"(a), "l"(b)); return d;
}
__device__ __forceinline__ u64 f2fma(u64 a, u64 b, u64 c) {
    u64 d; asm("fma.rn.f32x2 %0,%1,%2,%3;" : "=l"(d) : "l"(a), "l"(b), "l"(c)); return d;
}
__device__ __forceinline__ u64 f2add(u64 a, u64 b) {
    u64 d; asm("add.rn.f32x2 %0,%1,%2;" : "=l"(d) : "l"(a), "l"(b)); return d;
}

// 256-bit load with direct L2::evict_last modifier (v8.b32 form — the only
// vector width ptxas accepts this modifier on, per sm_103a).
struct F8 { float f[8]; };
__device__ __forceinline__ F8 ldg256_el(const float* p) {
    F8 v;
    asm volatile("ld.global.nc.L2::evict_last.v8.b32 "
                 "{%0,%1,%2,%3,%4,%5,%6,%7}, [%8];"
                 : "=f"(v.f[0]), "=f"(v.f[1]), "=f"(v.f[2]), "=f"(v.f[3]),
                   "=f"(v.f[4]), "=f"(v.f[5]), "=f"(v.f[6]), "=f"(v.f[7])
                 : "l"(p));
    return v;
}

// One-warp setup: fold norms into coefficients, pack, store to global table.
__global__ void setup_coeffs_kernel(const float* __restrict__ coeffs) {
    if (threadIdx.x == 0) {
        float c[14];
#pragma unroll
        for (int k = 0; k < 14; k++) c[k] = coeffs[k];
        float ac[14];
        ac[0]  =  Y00f * 2.0f * c[0];
        ac[1]  =  Y00f * K20f * c[1];
        ac[2]  =  N10f * K21f * c[3];
        ac[3]  = -N10f * K21f * c[4];
        ac[4]  = -N10f * K21f * c[2];
        ac[5]  =  Y00f * K30f * c[5];
        ac[6]  =  N10f * K31f * c[7];
        ac[7]  = -N10f * K31f * c[8];
        ac[8]  = -N10f * K31f * c[6];
        ac[9]  =  N20f * K32f * c[11];
        ac[10] =  C21f * K32f * c[12];
        ac[11] =  C21f * K32f * c[10];
        ac[12] =  C22f * K32f * c[13];
        ac[13] =  C22f * K32f * c[9];
#pragma unroll
        for (int k = 0; k < 14; k++) g_A[k] = pk(ac[k], ac[k]);
    }
}

// Per-point scalar prep: MUFU ops + constant-immediate ops (FFMA-imm rt=1).
struct Prep { float r, t, ct, st, cp, sp, rho, tmr, fmr, l30, nspsq, ct2t; };

__device__ __forceinline__ Prep prep(float r, float th, float ph) {
    Prep p;
    p.r = r;
    __sincosf(th, &p.st, &p.ct);
    __sincosf(ph, &p.sp, &p.cp);
    p.t     = __expf(r * (-1.0f / 6.0f));      // e^{-r/6}
    p.rho   = r * (2.0f / 3.0f);
    p.tmr   = 2.0f - r;
    p.fmr   = 4.0f - p.rho;
    p.l30   = fmaf(p.rho - 6.0f, p.rho, 6.0f); // rho^2 - 6 rho + 6
    p.nspsq = p.sp * (-p.sp);                  // -sin^2(phi)
    p.ct2t  = fmaf(p.ct * p.ct, 1.5f, -0.5f);  // (3cos^2-1)/2
    return p;
}

// Packed evaluation of two points; a[] loads rematerialize as L1 hits.
__device__ __forceinline__ u64 eval_pair(const Prep& p0, const Prep& p1, const u64* a) {
    u64 R   = pk(p0.r,   p1.r),   T    = pk(p0.t,    p1.t);
    u64 CT  = pk(p0.ct,  p1.ct),  ST   = pk(p0.st,   p1.st);
    u64 CP  = pk(p0.cp,  p1.cp),  SP   = pk(p0.sp,   p1.sp);
    u64 RHO = pk(p0.rho, p1.rho), TMR  = pk(p0.tmr,  p1.tmr);
    u64 FMR = pk(p0.fmr, p1.fmr), L30  = pk(p0.l30,  p1.l30);
    u64 NSQ = pk(p0.nspsq, p1.nspsq), CT2T = pk(p0.ct2t, p1.ct2t);

    u64 T2 = f2mul(T, T), T3 = f2mul(T2, T), T6 = f2mul(T3, T3);
    u64 G3 = f2mul(FMR, RHO);           // (4-rho)*rho
    u64 Q  = f2mul(RHO, RHO);           // rho^2
    u64 C2P  = f2fma(CP, CP, NSQ);      // cos(2phi)
    u64 SPCP = f2mul(SP, CP);
    u64 S2P  = f2add(SPCP, SPCP);       // sin(2phi)
    u64 CTST = f2mul(CT, ST), ST2 = f2mul(ST, ST);

    // n=2 block (×t3)
    u64 X1 = f2fma(CP, a[3], f2mul(SP, a[4]));
    X1     = f2fma(CT, a[2], f2mul(ST, X1));
    u64 B3 = f2fma(TMR, a[1], f2mul(R, X1));

    // n=3, l=0..1 block (×t2)
    u64 X2 = f2fma(CP, a[7], f2mul(SP, a[8]));
    X2     = f2fma(CT, a[6], f2mul(ST, X2));
    u64 P2 = f2fma(L30, a[5], f2mul(G3, X2));

    // n=3, l=2 block
    u64 Y = f2fma(CP, a[10], f2mul(SP, a[11]));
    Y     = f2mul(CTST, Y);
    u64 Z = f2fma(C2P, a[12], f2mul(S2P, a[13]));
    u64 W = f2fma(ST2, Z, f2fma(CT2T, a[9], Y));
    u64 B2 = f2fma(Q, W, P2);

    return f2fma(T6, a[0], f2fma(T3, B3, f2mul(T2, B2)));
}

__global__ __launch_bounds__(128)
void orbital_eval_kernel(const float* __restrict__ pos,
                         float* __restrict__ out,
                         int n8, int n) {
    int i = blockIdx.x * blockDim.x + threadIdx.x;

    // Load pre-packed combined coefficients (7x 16B, L1-broadcast).
    u64 a[14];
    {
        const ulonglong2* Ap = reinterpret_cast<const ulonglong2*>(g_A);
#pragma unroll
        for (int k = 0; k < 7; k++) {
            ulonglong2 v = __ldg(&Ap[k]);
            a[2 * k]     = v.x;
            a[2 * k + 1] = v.y;
        }
    }

    if (i < n8) {
        // 3x 256-bit evict_last loads: 8 points (24 floats), 32B-aligned.
        const float* base = pos + (size_t)i * 24;
        F8 A0 = ldg256_el(base);        // f0..f7
        F8 A1 = ldg256_el(base + 8);    // f8..f15
        F8 A2 = ldg256_el(base + 16);   // f16..f23

        float2* o2 = reinterpret_cast<float2*>(out);

        // Points 0..3: (f0,f1,f2)(f3,f4,f5)(f6,f7,f8)(f9,f10,f11)
        {
            Prep q0 = prep(A0.f[0], A0.f[1], A0.f[2]);
            Prep q1 = prep(A0.f[3], A0.f[4], A0.f[5]);
            u64 r01 = eval_pair(q0, q1, a);
            float2 o; upk(r01, o.x, o.y);
            __stcs(&o2[4 * i], o);
            Prep q2 = prep(A0.f[6], A0.f[7], A1.f[0]);
            Prep q3 = prep(A1.f[1], A1.f[2], A1.f[3]);
            u64 r23 = eval_pair(q2, q3, a);
            upk(r23, o.x, o.y);
            __stcs(&o2[4 * i + 1], o);
        }
        // Points 4..7: (f12,f13,f14)(f15,f16,f17)(f18,f19,f20)(f21,f22,f23)
        {
            Prep q4 = prep(A1.f[4], A1.f[5], A1.f[6]);
            Prep q5 = prep(A1.f[7], A2.f[0], A2.f[1]);
            u64 r45 = eval_pair(q4, q5, a);
            float2 o; upk(r45, o.x, o.y);
            __stcs(&o2[4 * i + 2], o);
            Prep q6 = prep(A2.f[2], A2.f[3], A2.f[4]);
            Prep q7 = prep(A2.f[5], A2.f[6], A2.f[7]);
            u64 r67 = eval_pair(q6, q7, a);
            upk(r67, o.x, o.y);
            __stcs(&o2[4 * i + 3], o);
        }
    }

    // Scalar tail (n % 8 != 0) — not exercised for 2048x4096 but kept correct.
    int tail = n - n8 * 8;
    if (i < tail) {
        int idx = n8 * 8 + i;
        Prep p = prep(pos[3 * idx], pos[3 * idx + 1], pos[3 * idx + 2]);
        u64 rr = eval_pair(p, p, a);
        float lo, hi; upk(rr, lo, hi);
        out[idx] = lo;
    }
}

extern "C" void kernel_launch(void* const* d_in, const int* in_sizes, int n_in,
                              void* d_out, int out_size) {
    const float* pos    = (const float*)d_in[0];   // (2048, 4096, 3) fp32
    const float* coeffs = (const float*)d_in[1];   // (14,) fp32
    float* out          = (float*)d_out;           // (2048, 4096) fp32

    int n  = out_size;
    int n8 = n / 8;

    setup_coeffs_kernel<<<1, 32>>>(coeffs);

    int threads = 128;
    int groups  = (n8 > 0) ? n8 : 1;
    int blocks  = (groups + threads - 1) / threads;
    orbital_eval_kernel<<<blocks, threads>>>(pos, out, n8, n);
}